// round 9
// baseline (speedup 1.0000x reference)
#include <cuda_runtime.h>

// Problem constants
#define B_SZ    16
#define L_LEN   2048
#define H_DIM   512
#define N_DIM   512
#define T_CH    16                 // chunk length
#define C_CH    (L_LEN / T_CH)     // 128 chunks
#define OUT_MAIN (B_SZ * L_LEN * N_DIM)
#define BPAD    20                 // proj smem pad (floats)

// scan_tf32 smem geometry (floats)
#define ASTR    12                 // A-slab row stride: 8 k + 4 pad (conflict-free)
#define SLABF   (N_DIM * ASTR)     // 6144 floats = 24 KB per (buf,split)
#define H1_OFF  (4 * SLABF)        // 24576
#define HSTR    24                 // h row stride (conflict-free)
#define H2_OFF  (H1_OFF + N_DIM * HSTR)            // 36864
#define SMEM_FLOATS (H2_OFF + N_DIM * HSTR)        // 49152
#define SCAN_SMEM_BYTES (SMEM_FLOATS * 4)          // 196608

// ---------------- scratch (device globals; no allocations allowed) ----------
__device__ float g_bx[L_LEN * N_DIM * B_SZ];   // Bx projections  [t][n][b]  (64MB)
__device__ float g_f [C_CH * B_SZ * N_DIM];    // chunk local finals [c][b][n]
__device__ float g_XA[C_CH * B_SZ * N_DIM];    // Kogge-Stone ping
__device__ float g_XB[C_CH * B_SZ * N_DIM];    // Kogge-Stone pong
__device__ float g_P1[N_DIM * N_DIM];
__device__ float g_P2[N_DIM * N_DIM];
__device__ float g_Mp[7 * N_DIM * N_DIM];      // M^(2^d), M = A^16, d=0..6
__device__ float g_A1t[N_DIM * N_DIM];         // tf32 hi split, [k8][row][8] blocked
__device__ float g_A2t[N_DIM * N_DIM];         // tf32 lo split, same layout

// ---------------- tf32 helpers ----------------------------------------------
__device__ __forceinline__ float tf32r(float x)
{
    unsigned y;
    asm("cvt.rna.tf32.f32 %0, %1;" : "=r"(y) : "f"(x));
    return __uint_as_float(y);
}

#define MMATF32(d, a, b) \
    asm volatile("mma.sync.aligned.m16n8k8.row.col.f32.tf32.tf32.f32 " \
        "{%0,%1,%2,%3}, {%4,%5,%6,%7}, {%8,%9}, {%0,%1,%2,%3};" \
        : "+f"((d)[0]), "+f"((d)[1]), "+f"((d)[2]), "+f"((d)[3]) \
        : "r"((a)[0]), "r"((a)[1]), "r"((a)[2]), "r"((a)[3]), \
          "r"((b)[0]), "r"((b)[1]))

// ---------------- cp.async primitives ---------------------------------------
__device__ __forceinline__ void cpa16(unsigned dst, const void* src)
{
    asm volatile("cp.async.cg.shared.global [%0], [%1], 16;"
                 :: "r"(dst), "l"(src) : "memory");
}
#define CP_COMMIT() asm volatile("cp.async.commit_group;" ::: "memory")
#define CP_WAIT1()  asm volatile("cp.async.wait_group 1;" ::: "memory")
#define CP_WAIT0()  asm volatile("cp.async.wait_group 0;" ::: "memory")

// ---------------- packed fp32x2 (proj / matsq) -------------------------------
typedef unsigned long long u64;
#define FFMA2(acc, apk, hpk) \
    asm("fma.rn.f32x2 %0, %1, %2, %0;" : "+l"(acc) : "l"(apk), "l"(hpk))
#define PACK2(dst, f) \
    asm("mov.b64 %0, {%1, %1};" : "=l"(dst) : "f"(f))
#define UNPK(lo, hi, src) \
    asm("mov.b64 {%0, %1}, %2;" : "=f"(lo), "=f"(hi) : "l"(src))

#define ONEK(base, off, c0, c1, c2, c3) do {                                   \
    const ulonglong2 hvp = *reinterpret_cast<const ulonglong2*>((base) + (off) * BPAD); \
    u64 ap;                                                                    \
    PACK2(ap, c0); FFMA2(acc0p[0], ap, hvp.x); FFMA2(acc0p[1], ap, hvp.y);     \
    PACK2(ap, c1); FFMA2(acc1p[0], ap, hvp.x); FFMA2(acc1p[1], ap, hvp.y);     \
    PACK2(ap, c2); FFMA2(acc2p[0], ap, hvp.x); FFMA2(acc2p[1], ap, hvp.y);     \
    PACK2(ap, c3); FFMA2(acc3p[0], ap, hvp.x); FFMA2(acc3p[1], ap, hvp.y);     \
} while (0)

#define QUAD_FMA(base, k4) do {                                                \
    ONEK(base, 4*(k4) + 0, Av0.x, Av1.x, Av2.x, Av3.x);                        \
    ONEK(base, 4*(k4) + 1, Av0.y, Av1.y, Av2.y, Av3.y);                        \
    ONEK(base, 4*(k4) + 2, Av0.z, Av1.z, Av2.z, Av3.z);                        \
    ONEK(base, 4*(k4) + 3, Av0.w, Av1.w, Av2.w, Av3.w);                        \
} while (0)

// ---------------- prep: A (fp32) -> tf32 split, k8-blocked ------------------
__global__ __launch_bounds__(256) void prep_kernel(const float* __restrict__ A)
{
    const int idx = blockIdx.x * 256 + threadIdx.x;      // 262144 total
    const int row = idx >> 9;
    const int k   = idx & 511;
    const int kc  = k >> 3, kk = k & 7;
    const float a = A[idx];
    const float a1 = tf32r(a);
    const float a2 = tf32r(a - a1);
    const int dst = kc * (N_DIM * 8) + row * 8 + kk;
    g_A1t[dst] = a1;
    g_A2t[dst] = a2;
}

// ---------------- Phase 1: bx[t][n][b] = sum_h Bm[n][h] * x[b][t][h] -------
__global__ __launch_bounds__(512) void proj_kernel(const float* __restrict__ x,
                                                   const float* __restrict__ Bm)
{
    __shared__ float xs[H_DIM * BPAD];         // [h][b], 40 KB
    const int t  = blockIdx.x;
    const int bg = threadIdx.x & 3;
    const int rg = threadIdx.x >> 2;

    {
        const int k = threadIdx.x;
        #pragma unroll
        for (int b = 0; b < B_SZ; b++)
            xs[k * BPAD + b] = x[((size_t)b * L_LEN + t) * H_DIM + k];
    }
    __syncthreads();

    u64 acc0p[2] = {0,0}, acc1p[2] = {0,0}, acc2p[2] = {0,0}, acc3p[2] = {0,0};

    const int n0 = rg * 4;
    const float4* w0 = reinterpret_cast<const float4*>(Bm + (size_t)(n0 + 0) * H_DIM);
    const float4* w1 = reinterpret_cast<const float4*>(Bm + (size_t)(n0 + 1) * H_DIM);
    const float4* w2 = reinterpret_cast<const float4*>(Bm + (size_t)(n0 + 2) * H_DIM);
    const float4* w3 = reinterpret_cast<const float4*>(Bm + (size_t)(n0 + 3) * H_DIM);
    const float* xp = xs + bg * 4;

    #pragma unroll 2
    for (int k4 = 0; k4 < H_DIM / 4; k4++) {
        const float4 Av0 = w0[k4], Av1 = w1[k4], Av2 = w2[k4], Av3 = w3[k4];
        QUAD_FMA(xp, k4);
    }

    // store [t][n][b]
    {
        float l0,h0,l1,h1;
        float4 v;
        UNPK(l0,h0, acc0p[0]); UNPK(l1,h1, acc0p[1]);
        v.x=l0; v.y=h0; v.z=l1; v.w=h1;
        *reinterpret_cast<float4*>(g_bx + ((size_t)t * N_DIM + n0 + 0) * B_SZ + bg*4) = v;
        UNPK(l0,h0, acc1p[0]); UNPK(l1,h1, acc1p[1]);
        v.x=l0; v.y=h0; v.z=l1; v.w=h1;
        *reinterpret_cast<float4*>(g_bx + ((size_t)t * N_DIM + n0 + 1) * B_SZ + bg*4) = v;
        UNPK(l0,h0, acc2p[0]); UNPK(l1,h1, acc2p[1]);
        v.x=l0; v.y=h0; v.z=l1; v.w=h1;
        *reinterpret_cast<float4*>(g_bx + ((size_t)t * N_DIM + n0 + 2) * B_SZ + bg*4) = v;
        UNPK(l0,h0, acc3p[0]); UNPK(l1,h1, acc3p[1]);
        v.x=l0; v.y=h0; v.z=l1; v.w=h1;
        *reinterpret_cast<float4*>(g_bx + ((size_t)t * N_DIM + n0 + 3) * B_SZ + bg*4) = v;
    }
}

// ---------------- SGEMM: Y = X @ X (512x512), 32x32 tiles -------------------
__device__ __forceinline__ const float* mat_sel(const float* Aext, int s)
{
    if (s == 0) return Aext;
    if (s == 1) return g_P1;
    if (s == 2) return g_P2;
    return g_Mp + (size_t)(s - 10) * N_DIM * N_DIM;
}
__device__ __forceinline__ float* mat_sel_w(int s)
{
    if (s == 1) return g_P1;
    if (s == 2) return g_P2;
    return g_Mp + (size_t)(s - 10) * N_DIM * N_DIM;
}

__global__ __launch_bounds__(128) void matsq_kernel(const float* __restrict__ Aext,
                                                    int src_sel, int dst_sel)
{
    const float* __restrict__ X = mat_sel(Aext, src_sel);
    float* __restrict__ Y = mat_sel_w(dst_sel);

    __shared__ float As[32][34];
    __shared__ float Bs[32][36];
    const int tid = threadIdx.x;
    const int tx = tid & 7;
    const int ty = tid >> 3;
    const int i0 = blockIdx.y * 32, j0 = blockIdx.x * 32;

    u64 acc0[2] = {0,0}, acc1[2] = {0,0};

    const int lrow = tid >> 2;
    const int lq   = tid & 3;

    for (int kt = 0; kt < N_DIM; kt += 32) {
        {
            const float4 v1 = *reinterpret_cast<const float4*>(X + (size_t)(i0 + lrow) * N_DIM + kt + lq * 8);
            const float4 v2 = *reinterpret_cast<const float4*>(X + (size_t)(i0 + lrow) * N_DIM + kt + lq * 8 + 4);
            As[lq*8 + 0][lrow] = v1.x; As[lq*8 + 1][lrow] = v1.y;
            As[lq*8 + 2][lrow] = v1.z; As[lq*8 + 3][lrow] = v1.w;
            As[lq*8 + 4][lrow] = v2.x; As[lq*8 + 5][lrow] = v2.y;
            As[lq*8 + 6][lrow] = v2.z; As[lq*8 + 7][lrow] = v2.w;
        }
        {
            const float4 v1 = *reinterpret_cast<const float4*>(X + (size_t)(kt + lrow) * N_DIM + j0 + lq * 8);
            const float4 v2 = *reinterpret_cast<const float4*>(X + (size_t)(kt + lrow) * N_DIM + j0 + lq * 8 + 4);
            *reinterpret_cast<float4*>(&Bs[lrow][lq*8])     = v1;
            *reinterpret_cast<float4*>(&Bs[lrow][lq*8 + 4]) = v2;
        }
        __syncthreads();

        #pragma unroll
        for (int kk = 0; kk < 32; kk++) {
            const float2 a = *reinterpret_cast<const float2*>(&As[kk][ty * 2]);
            const ulonglong2 bv = *reinterpret_cast<const ulonglong2*>(&Bs[kk][tx * 4]);
            u64 ap;
            PACK2(ap, a.x); FFMA2(acc0[0], ap, bv.x); FFMA2(acc0[1], ap, bv.y);
            PACK2(ap, a.y); FFMA2(acc1[0], ap, bv.x); FFMA2(acc1[1], ap, bv.y);
        }
        __syncthreads();
    }

    {
        float l0,h0,l1,h1;
        UNPK(l0,h0, acc0[0]); UNPK(l1,h1, acc0[1]);
        float4 v; v.x=l0; v.y=h0; v.z=l1; v.w=h1;
        *reinterpret_cast<float4*>(Y + (size_t)(i0 + ty*2 + 0) * N_DIM + j0 + tx*4) = v;
        UNPK(l0,h0, acc1[0]); UNPK(l1,h1, acc1[1]);
        v.x=l0; v.y=h0; v.z=l1; v.w=h1;
        *reinterpret_cast<float4*>(Y + (size_t)(i0 + ty*2 + 1) * N_DIM + j0 + tx*4) = v;
    }
}

// ---------------- Kogge-Stone level: x'_c = M^(2^d) x_{c-2^d} + x_c --------
__device__ __forceinline__ const float* ks_sel(int s)
{
    if (s == 0) return g_f;
    return (s == 1) ? g_XA : g_XB;
}
__device__ __forceinline__ float* ks_sel_w(int s)
{
    return (s == 1) ? g_XA : g_XB;
}

__global__ __launch_bounds__(512) void ks_level_kernel(int d, int src_sel, int dst_sel)
{
    const float* __restrict__ src = ks_sel(src_sel);
    float* __restrict__ dst = ks_sel_w(dst_sel);
    const int c = blockIdx.x;
    const int shift = 1 << d;

    if (c < shift) {
        const int n = threadIdx.x;
        #pragma unroll
        for (int b = 0; b < B_SZ; b++)
            dst[((size_t)c * B_SZ + b) * N_DIM + n] = src[((size_t)c * B_SZ + b) * N_DIM + n];
        return;
    }

    __shared__ float xs[N_DIM * BPAD];         // x_{c-shift} as [k][b]
    const float* __restrict__ M = g_Mp + (size_t)d * N_DIM * N_DIM;
    const int bg = threadIdx.x & 3;
    const int rg = threadIdx.x >> 2;
    const int n0 = rg * 4;

    {
        const int k = threadIdx.x;
        const float* sp = src + (size_t)(c - shift) * B_SZ * N_DIM;
        #pragma unroll
        for (int b = 0; b < B_SZ; b++)
            xs[k * BPAD + b] = sp[(size_t)b * N_DIM + k];
    }
    __syncthreads();

    float acc0[4], acc1[4], acc2[4], acc3[4];
    #pragma unroll
    for (int bb = 0; bb < 4; bb++) {
        const float4 v = *reinterpret_cast<const float4*>(
            src + ((size_t)c * B_SZ + (bg*4 + bb)) * N_DIM + n0);
        acc0[bb] = v.x; acc1[bb] = v.y; acc2[bb] = v.z; acc3[bb] = v.w;
    }

    const float4* m0 = reinterpret_cast<const float4*>(M + (size_t)(n0 + 0) * N_DIM);
    const float4* m1 = reinterpret_cast<const float4*>(M + (size_t)(n0 + 1) * N_DIM);
    const float4* m2 = reinterpret_cast<const float4*>(M + (size_t)(n0 + 2) * N_DIM);
    const float4* m3 = reinterpret_cast<const float4*>(M + (size_t)(n0 + 3) * N_DIM);
    const float* xp = xs + bg * 4;

    #pragma unroll 2
    for (int k4 = 0; k4 < N_DIM / 4; k4++) {
        const float4 Av0 = m0[k4], Av1 = m1[k4], Av2 = m2[k4], Av3 = m3[k4];
        const int k = 4 * k4;
        #pragma unroll
        for (int kk = 0; kk < 4; kk++) {
            const float a0v = (&Av0.x)[kk], a1v = (&Av1.x)[kk],
                        a2v = (&Av2.x)[kk], a3v = (&Av3.x)[kk];
            const float4 hv = *reinterpret_cast<const float4*>(xp + (k + kk) * BPAD);
            acc0[0] += a0v*hv.x; acc0[1] += a0v*hv.y; acc0[2] += a0v*hv.z; acc0[3] += a0v*hv.w;
            acc1[0] += a1v*hv.x; acc1[1] += a1v*hv.y; acc1[2] += a1v*hv.z; acc1[3] += a1v*hv.w;
            acc2[0] += a2v*hv.x; acc2[1] += a2v*hv.y; acc2[2] += a2v*hv.z; acc2[3] += a2v*hv.w;
            acc3[0] += a3v*hv.x; acc3[1] += a3v*hv.y; acc3[2] += a3v*hv.z; acc3[3] += a3v*hv.w;
        }
    }

    #pragma unroll
    for (int bb = 0; bb < 4; bb++) {
        float4 v; v.x = acc0[bb]; v.y = acc1[bb]; v.z = acc2[bb]; v.w = acc3[bb];
        *reinterpret_cast<float4*>(
            dst + ((size_t)c * B_SZ + (bg*4 + bb)) * N_DIM + n0) = v;
    }
}

// ---------------- tf32 chunk scan (one CTA per chunk) ------------------------
// h in smem as fp32 tf32-rounded split (h1 + h2); A streamed via cp.async
// double buffering: one barrier per k-iteration, loads fully overlapped.
template <bool FIRST_PASS>
__global__ __launch_bounds__(512) void scan_tf32_kernel(float* __restrict__ out,
                                                        int out_size)
{
    extern __shared__ float smf[];
    float* h1s = smf + H1_OFF;
    float* h2s = smf + H2_OFF;

    const int c    = blockIdx.x;
    const int tid  = threadIdx.x;
    const int warp = tid >> 5;
    const int lane = tid & 31;
    const int g    = lane >> 2;          // groupID 0..7
    const int t    = lane & 3;           // threadID_in_group 0..3
    const int row0 = warp * 32;

    const unsigned sb = (unsigned)__cvta_generic_to_shared(smf);

    // ---- init h split ----
    if (FIRST_PASS || c == 0) {
        #pragma unroll
        for (int b = 0; b < B_SZ; b++) {
            h1s[tid * HSTR + b] = 0.0f;
            h2s[tid * HSTR + b] = 0.0f;
        }
    } else {
        const float* sp = g_XA + (size_t)(c - 1) * B_SZ * N_DIM;
        #pragma unroll
        for (int b = 0; b < B_SZ; b++) {
            const float v  = sp[(size_t)b * N_DIM + tid];
            const float v1 = tf32r(v);
            h1s[tid * HSTR + b] = v1;
            h2s[tid * HSTR + b] = tf32r(v - v1);
        }
    }

    // issue slab 0 into buf 0 (async; completion awaited inside k-loop)
    {
        const float* s1 = g_A1t + tid * 8;
        const float* s2 = g_A2t + tid * 8;
        const unsigned d1 = sb + (0 * SLABF + tid * ASTR) * 4;
        const unsigned d2 = sb + (1 * SLABF + tid * ASTR) * 4;
        cpa16(d1, s1); cpa16(d1 + 16, s1 + 4);
        cpa16(d2, s2); cpa16(d2 + 16, s2 + 4);
        CP_COMMIT();
    }

    for (int j = 0; j < T_CH; j++) {
        const int tt = c * T_CH + j;

        // ---- acc init from bx[t][n][b] ----
        float acc[2][2][4];
        #pragma unroll
        for (int mt = 0; mt < 2; mt++) {
            const int n = row0 + mt * 16 + g;
            #pragma unroll
            for (int nt = 0; nt < 2; nt++) {
                const int b = nt * 8 + t * 2;
                const float2 vlo = *reinterpret_cast<const float2*>(
                    g_bx + ((size_t)tt * N_DIM + n) * B_SZ + b);
                const float2 vhi = *reinterpret_cast<const float2*>(
                    g_bx + ((size_t)tt * N_DIM + n + 8) * B_SZ + b);
                acc[mt][nt][0] = vlo.x; acc[mt][nt][1] = vlo.y;
                acc[mt][nt][2] = vhi.x; acc[mt][nt][3] = vhi.y;
            }
        }

        // ---- k loop: one barrier per iteration, cp.async double-buffered ----
        for (int kc = 0; kc < 64; kc++) {
            // barrier: separates prior reads of buf[(kc+1)&1] (iter kc-1) and
            // h writes (prev step) from the writes/reads below
            __syncthreads();

            const bool more = (kc + 1 < 64);
            if (more) {
                const int nb = (kc + 1) & 1;
                const float* s1 = g_A1t + (size_t)(kc + 1) * (N_DIM * 8) + tid * 8;
                const float* s2 = g_A2t + (size_t)(kc + 1) * (N_DIM * 8) + tid * 8;
                const unsigned d1 = sb + ((nb * 2 + 0) * SLABF + tid * ASTR) * 4;
                const unsigned d2 = sb + ((nb * 2 + 1) * SLABF + tid * ASTR) * 4;
                cpa16(d1, s1); cpa16(d1 + 16, s1 + 4);
                cpa16(d2, s2); cpa16(d2 + 16, s2 + 4);
                CP_COMMIT();
                CP_WAIT1();            // slab kc complete
            } else {
                CP_WAIT0();            // drain last slab
            }

            const float* Ab1 = smf + ((kc & 1) * 2 + 0) * SLABF;
            const float* Ab2 = smf + ((kc & 1) * 2 + 1) * SLABF;

            unsigned a1f[2][4], a2f[2][4];
            #pragma unroll
            for (int mt = 0; mt < 2; mt++) {
                const int rb = row0 + mt * 16;
                a1f[mt][0] = __float_as_uint(Ab1[(rb + g    ) * ASTR + t    ]);
                a1f[mt][1] = __float_as_uint(Ab1[(rb + g + 8) * ASTR + t    ]);
                a1f[mt][2] = __float_as_uint(Ab1[(rb + g    ) * ASTR + t + 4]);
                a1f[mt][3] = __float_as_uint(Ab1[(rb + g + 8) * ASTR + t + 4]);
                a2f[mt][0] = __float_as_uint(Ab2[(rb + g    ) * ASTR + t    ]);
                a2f[mt][1] = __float_as_uint(Ab2[(rb + g + 8) * ASTR + t    ]);
                a2f[mt][2] = __float_as_uint(Ab2[(rb + g    ) * ASTR + t + 4]);
                a2f[mt][3] = __float_as_uint(Ab2[(rb + g + 8) * ASTR + t + 4]);
            }

            const int kr = kc * 8;
            unsigned b1f[2][2], b2f[2][2];
            #pragma unroll
            for (int nt = 0; nt < 2; nt++) {
                const int col = nt * 8 + g;
                b1f[nt][0] = __float_as_uint(h1s[(kr + t    ) * HSTR + col]);
                b1f[nt][1] = __float_as_uint(h1s[(kr + t + 4) * HSTR + col]);
                b2f[nt][0] = __float_as_uint(h2s[(kr + t    ) * HSTR + col]);
                b2f[nt][1] = __float_as_uint(h2s[(kr + t + 4) * HSTR + col]);
            }

            #pragma unroll
            for (int mt = 0; mt < 2; mt++) {
                #pragma unroll
                for (int nt = 0; nt < 2; nt++) {
                    MMATF32(acc[mt][nt], a1f[mt], b1f[nt]);
                    MMATF32(acc[mt][nt], a1f[mt], b2f[nt]);
                    MMATF32(acc[mt][nt], a2f[mt], b1f[nt]);
                }
            }
        }

        // all reads of h done (kc=63 computed) -> safe to overwrite after sync
        __syncthreads();

        // issue slab 0 for next step (overlaps with h write-back)
        if (j + 1 < T_CH) {
            const float* s1 = g_A1t + tid * 8;
            const float* s2 = g_A2t + tid * 8;
            const unsigned d1 = sb + (0 * SLABF + tid * ASTR) * 4;
            const unsigned d2 = sb + (1 * SLABF + tid * ASTR) * 4;
            cpa16(d1, s1); cpa16(d1 + 16, s1 + 4);
            cpa16(d2, s2); cpa16(d2 + 16, s2 + 4);
            CP_COMMIT();
        }

        // ---- write-back: h split (tf32-rounded), outputs, finals ----
        #pragma unroll
        for (int mt = 0; mt < 2; mt++) {
            #pragma unroll
            for (int nt = 0; nt < 2; nt++) {
                const int b = nt * 8 + t * 2;
                #pragma unroll
                for (int hh = 0; hh < 2; hh++) {
                    const int n = row0 + mt * 16 + g + hh * 8;
                    const float v0 = acc[mt][nt][hh * 2 + 0];
                    const float v1 = acc[mt][nt][hh * 2 + 1];
                    const float p0 = tf32r(v0), p1v = tf32r(v1);
                    h1s[n * HSTR + b]     = p0;
                    h1s[n * HSTR + b + 1] = p1v;
                    h2s[n * HSTR + b]     = tf32r(v0 - p0);
                    h2s[n * HSTR + b + 1] = tf32r(v1 - p1v);

                    if (!FIRST_PASS) {
                        out[((size_t)(b)     * L_LEN + tt) * N_DIM + n] = v0;
                        out[((size_t)(b + 1) * L_LEN + tt) * N_DIM + n] = v1;
                    }
                    if (FIRST_PASS && j == T_CH - 1) {
                        g_f[((size_t)c * B_SZ + b)     * N_DIM + n] = v0;
                        g_f[((size_t)c * B_SZ + b + 1) * N_DIM + n] = v1;
                    }
                    if (!FIRST_PASS && c == C_CH - 1 && j == T_CH - 1 &&
                        out_size >= OUT_MAIN + N_DIM * B_SZ) {
                        out[OUT_MAIN + (size_t)n * B_SZ + b]     = v0;
                        out[OUT_MAIN + (size_t)n * B_SZ + b + 1] = v1;
                    }
                }
            }
        }
    }
}

// ---------------- launch ----------------------------------------------------
extern "C" void kernel_launch(void* const* d_in, const int* in_sizes, int n_in,
                              void* d_out, int out_size)
{
    const float* x  = (const float*)d_in[0];   // (B, L, H)
    const float* A  = (const float*)d_in[1];   // (N, N)
    const float* Bm = (const float*)d_in[2];   // (N, H)
    float* out = (float*)d_out;

    cudaFuncSetAttribute(scan_tf32_kernel<true>,
                         cudaFuncAttributeMaxDynamicSharedMemorySize, SCAN_SMEM_BYTES);
    cudaFuncSetAttribute(scan_tf32_kernel<false>,
                         cudaFuncAttributeMaxDynamicSharedMemorySize, SCAN_SMEM_BYTES);

    dim3 sgrid(N_DIM / 32, N_DIM / 32);

    // harness poison launch occupies overall slot #1; put scan1 at our slot 5
    // so ncu (-s 5 -c 1) captures it.
    prep_kernel<<<N_DIM * N_DIM / 256, 256>>>(A);              // slot 1
    proj_kernel<<<L_LEN, 512>>>(x, Bm);                        // slot 2
    matsq_kernel<<<sgrid, 128>>>(A, 0, 1);                     // slot 3: A^2
    matsq_kernel<<<sgrid, 128>>>(A, 1, 2);                     // slot 4: A^4
    scan_tf32_kernel<true><<<C_CH, 512, SCAN_SMEM_BYTES>>>(nullptr, 0);  // slot 5

    matsq_kernel<<<sgrid, 128>>>(A, 2, 1);                     // A^8
    matsq_kernel<<<sgrid, 128>>>(A, 1, 10);                    // Mp[0] = A^16
    matsq_kernel<<<sgrid, 128>>>(A, 10, 11);                   // A^32
    matsq_kernel<<<sgrid, 128>>>(A, 11, 12);                   // A^64
    matsq_kernel<<<sgrid, 128>>>(A, 12, 13);                   // A^128
    matsq_kernel<<<sgrid, 128>>>(A, 13, 14);                   // A^256
    matsq_kernel<<<sgrid, 128>>>(A, 14, 15);                   // A^512
    matsq_kernel<<<sgrid, 128>>>(A, 15, 16);                   // A^1024

    ks_level_kernel<<<C_CH, 512>>>(0, 0, 1);
    ks_level_kernel<<<C_CH, 512>>>(1, 1, 2);
    ks_level_kernel<<<C_CH, 512>>>(2, 2, 1);
    ks_level_kernel<<<C_CH, 512>>>(3, 1, 2);
    ks_level_kernel<<<C_CH, 512>>>(4, 2, 1);
    ks_level_kernel<<<C_CH, 512>>>(5, 1, 2);
    ks_level_kernel<<<C_CH, 512>>>(6, 2, 1);   // final in XA

    scan_tf32_kernel<false><<<C_CH, 512, SCAN_SMEM_BYTES>>>(out, out_size);
}

// round 10
// speedup vs baseline: 1.6154x; 1.6154x over previous
#include <cuda_runtime.h>

// Problem constants
#define B_SZ    16
#define L_LEN   2048
#define H_DIM   512
#define N_DIM   512
#define T_CH    8                  // chunk length
#define C_CH    (L_LEN / T_CH)     // 256 chunks
#define CPC     2                  // chunks per CTA
#define OUT_MAIN (B_SZ * L_LEN * N_DIM)
#define BPAD    20                 // proj smem pad (floats)

// scan smem: h only, [col][k] layout, KSTR conflict-free (516 ≡ 4 mod 32)
#define NCOL    (CPC * B_SZ)       // 32 columns per CTA
#define KSTR    516
#define H2_OFF  (NCOL * KSTR)      // 16512
#define SCAN_SMEM_BYTES (2 * NCOL * KSTR * 4)   // 132096

// ---------------- scratch (device globals; no allocations allowed) ----------
__device__ float g_bx[L_LEN * N_DIM * B_SZ];   // Bx projections  [t][n][b]
__device__ float g_f [C_CH * B_SZ * N_DIM];    // chunk local finals [c][b][n]
__device__ float g_XA[C_CH * B_SZ * N_DIM];    // Kogge-Stone ping
__device__ float g_XB[C_CH * B_SZ * N_DIM];    // Kogge-Stone pong
__device__ float g_P1[N_DIM * N_DIM];
__device__ float g_P2[N_DIM * N_DIM];
__device__ float g_Mp[8 * N_DIM * N_DIM];      // M^(2^d), M = A^8, d=0..7
__device__ float g_A1t[N_DIM * N_DIM];         // tf32 hi split, [kc][row][8] blocked
__device__ float g_A2t[N_DIM * N_DIM];         // tf32 lo split, same layout

// ---------------- tf32 helpers ----------------------------------------------
__device__ __forceinline__ float tf32r(float x)
{
    unsigned y;
    asm("cvt.rna.tf32.f32 %0, %1;" : "=r"(y) : "f"(x));
    return __uint_as_float(y);
}

#define MMATF32(d, a, b) \
    asm volatile("mma.sync.aligned.m16n8k8.row.col.f32.tf32.tf32.f32 " \
        "{%0,%1,%2,%3}, {%4,%5,%6,%7}, {%8,%9}, {%0,%1,%2,%3};" \
        : "+f"((d)[0]), "+f"((d)[1]), "+f"((d)[2]), "+f"((d)[3]) \
        : "r"((a)[0]), "r"((a)[1]), "r"((a)[2]), "r"((a)[3]), \
          "r"((b)[0]), "r"((b)[1]))

// ---------------- packed fp32x2 (proj / matsq) -------------------------------
typedef unsigned long long u64;
#define FFMA2(acc, apk, hpk) \
    asm("fma.rn.f32x2 %0, %1, %2, %0;" : "+l"(acc) : "l"(apk), "l"(hpk))
#define PACK2(dst, f) \
    asm("mov.b64 %0, {%1, %1};" : "=l"(dst) : "f"(f))
#define UNPK(lo, hi, src) \
    asm("mov.b64 {%0, %1}, %2;" : "=f"(lo), "=f"(hi) : "l"(src))

#define ONEK(base, off, c0v, c1v, c2v, c3v) do {                               \
    const ulonglong2 hvp = *reinterpret_cast<const ulonglong2*>((base) + (off) * BPAD); \
    u64 ap;                                                                    \
    PACK2(ap, c0v); FFMA2(acc0p[0], ap, hvp.x); FFMA2(acc0p[1], ap, hvp.y);    \
    PACK2(ap, c1v); FFMA2(acc1p[0], ap, hvp.x); FFMA2(acc1p[1], ap, hvp.y);    \
    PACK2(ap, c2v); FFMA2(acc2p[0], ap, hvp.x); FFMA2(acc2p[1], ap, hvp.y);    \
    PACK2(ap, c3v); FFMA2(acc3p[0], ap, hvp.x); FFMA2(acc3p[1], ap, hvp.y);    \
} while (0)

#define QUAD_FMA(base, k4) do {                                                \
    ONEK(base, 4*(k4) + 0, Av0.x, Av1.x, Av2.x, Av3.x);                        \
    ONEK(base, 4*(k4) + 1, Av0.y, Av1.y, Av2.y, Av3.y);                        \
    ONEK(base, 4*(k4) + 2, Av0.z, Av1.z, Av2.z, Av3.z);                        \
    ONEK(base, 4*(k4) + 3, Av0.w, Av1.w, Av2.w, Av3.w);                        \
} while (0)

// ---------------- prep: A (fp32) -> tf32 split, k8-blocked ------------------
__global__ __launch_bounds__(256) void prep_kernel(const float* __restrict__ A)
{
    const int idx = blockIdx.x * 256 + threadIdx.x;
    const int row = idx >> 9;
    const int k   = idx & 511;
    const int kc  = k >> 3, kk = k & 7;
    const float a = A[idx];
    const float a1 = tf32r(a);
    const float a2 = tf32r(a - a1);
    const int dst = kc * (N_DIM * 8) + row * 8 + kk;
    g_A1t[dst] = a1;
    g_A2t[dst] = a2;
}

// ---------------- Phase 1: bx[t][n][b] = sum_h Bm[n][h] * x[b][t][h] -------
__global__ __launch_bounds__(512) void proj_kernel(const float* __restrict__ x,
                                                   const float* __restrict__ Bm)
{
    __shared__ float xs[H_DIM * BPAD];
    const int t  = blockIdx.x;
    const int bg = threadIdx.x & 3;
    const int rg = threadIdx.x >> 2;

    {
        const int k = threadIdx.x;
        #pragma unroll
        for (int b = 0; b < B_SZ; b++)
            xs[k * BPAD + b] = x[((size_t)b * L_LEN + t) * H_DIM + k];
    }
    __syncthreads();

    u64 acc0p[2] = {0,0}, acc1p[2] = {0,0}, acc2p[2] = {0,0}, acc3p[2] = {0,0};

    const int n0 = rg * 4;
    const float4* w0 = reinterpret_cast<const float4*>(Bm + (size_t)(n0 + 0) * H_DIM);
    const float4* w1 = reinterpret_cast<const float4*>(Bm + (size_t)(n0 + 1) * H_DIM);
    const float4* w2 = reinterpret_cast<const float4*>(Bm + (size_t)(n0 + 2) * H_DIM);
    const float4* w3 = reinterpret_cast<const float4*>(Bm + (size_t)(n0 + 3) * H_DIM);
    const float* xp = xs + bg * 4;

    #pragma unroll 2
    for (int k4 = 0; k4 < H_DIM / 4; k4++) {
        const float4 Av0 = w0[k4], Av1 = w1[k4], Av2 = w2[k4], Av3 = w3[k4];
        QUAD_FMA(xp, k4);
    }

    {
        float l0,h0,l1,h1;
        float4 v;
        UNPK(l0,h0, acc0p[0]); UNPK(l1,h1, acc0p[1]);
        v.x=l0; v.y=h0; v.z=l1; v.w=h1;
        *reinterpret_cast<float4*>(g_bx + ((size_t)t * N_DIM + n0 + 0) * B_SZ + bg*4) = v;
        UNPK(l0,h0, acc1p[0]); UNPK(l1,h1, acc1p[1]);
        v.x=l0; v.y=h0; v.z=l1; v.w=h1;
        *reinterpret_cast<float4*>(g_bx + ((size_t)t * N_DIM + n0 + 1) * B_SZ + bg*4) = v;
        UNPK(l0,h0, acc2p[0]); UNPK(l1,h1, acc2p[1]);
        v.x=l0; v.y=h0; v.z=l1; v.w=h1;
        *reinterpret_cast<float4*>(g_bx + ((size_t)t * N_DIM + n0 + 2) * B_SZ + bg*4) = v;
        UNPK(l0,h0, acc3p[0]); UNPK(l1,h1, acc3p[1]);
        v.x=l0; v.y=h0; v.z=l1; v.w=h1;
        *reinterpret_cast<float4*>(g_bx + ((size_t)t * N_DIM + n0 + 3) * B_SZ + bg*4) = v;
    }
}

// ---------------- SGEMM: Y = X @ X (512x512), 32x32 tiles -------------------
__device__ __forceinline__ const float* mat_sel(const float* Aext, int s)
{
    if (s == 0) return Aext;
    if (s == 1) return g_P1;
    if (s == 2) return g_P2;
    return g_Mp + (size_t)(s - 10) * N_DIM * N_DIM;
}
__device__ __forceinline__ float* mat_sel_w(int s)
{
    if (s == 1) return g_P1;
    if (s == 2) return g_P2;
    return g_Mp + (size_t)(s - 10) * N_DIM * N_DIM;
}

__global__ __launch_bounds__(128) void matsq_kernel(const float* __restrict__ Aext,
                                                    int src_sel, int dst_sel)
{
    const float* __restrict__ X = mat_sel(Aext, src_sel);
    float* __restrict__ Y = mat_sel_w(dst_sel);

    __shared__ float As[32][34];
    __shared__ float Bs[32][36];
    const int tid = threadIdx.x;
    const int tx = tid & 7;
    const int ty = tid >> 3;
    const int i0 = blockIdx.y * 32, j0 = blockIdx.x * 32;

    u64 acc0[2] = {0,0}, acc1[2] = {0,0};

    const int lrow = tid >> 2;
    const int lq   = tid & 3;

    for (int kt = 0; kt < N_DIM; kt += 32) {
        {
            const float4 v1 = *reinterpret_cast<const float4*>(X + (size_t)(i0 + lrow) * N_DIM + kt + lq * 8);
            const float4 v2 = *reinterpret_cast<const float4*>(X + (size_t)(i0 + lrow) * N_DIM + kt + lq * 8 + 4);
            As[lq*8 + 0][lrow] = v1.x; As[lq*8 + 1][lrow] = v1.y;
            As[lq*8 + 2][lrow] = v1.z; As[lq*8 + 3][lrow] = v1.w;
            As[lq*8 + 4][lrow] = v2.x; As[lq*8 + 5][lrow] = v2.y;
            As[lq*8 + 6][lrow] = v2.z; As[lq*8 + 7][lrow] = v2.w;
        }
        {
            const float4 v1 = *reinterpret_cast<const float4*>(X + (size_t)(kt + lrow) * N_DIM + j0 + lq * 8);
            const float4 v2 = *reinterpret_cast<const float4*>(X + (size_t)(kt + lrow) * N_DIM + j0 + lq * 8 + 4);
            *reinterpret_cast<float4*>(&Bs[lrow][lq*8])     = v1;
            *reinterpret_cast<float4*>(&Bs[lrow][lq*8 + 4]) = v2;
        }
        __syncthreads();

        #pragma unroll
        for (int kk = 0; kk < 32; kk++) {
            const float2 a = *reinterpret_cast<const float2*>(&As[kk][ty * 2]);
            const ulonglong2 bv = *reinterpret_cast<const ulonglong2*>(&Bs[kk][tx * 4]);
            u64 ap;
            PACK2(ap, a.x); FFMA2(acc0[0], ap, bv.x); FFMA2(acc0[1], ap, bv.y);
            PACK2(ap, a.y); FFMA2(acc1[0], ap, bv.x); FFMA2(acc1[1], ap, bv.y);
        }
        __syncthreads();
    }

    {
        float l0,h0,l1,h1;
        UNPK(l0,h0, acc0[0]); UNPK(l1,h1, acc0[1]);
        float4 v; v.x=l0; v.y=h0; v.z=l1; v.w=h1;
        *reinterpret_cast<float4*>(Y + (size_t)(i0 + ty*2 + 0) * N_DIM + j0 + tx*4) = v;
        UNPK(l0,h0, acc1[0]); UNPK(l1,h1, acc1[1]);
        v.x=l0; v.y=h0; v.z=l1; v.w=h1;
        *reinterpret_cast<float4*>(Y + (size_t)(i0 + ty*2 + 1) * N_DIM + j0 + tx*4) = v;
    }
}

// ---------------- Kogge-Stone level: x'_c = M^(8·2^d... ) x_{c-2^d} + x_c --
__device__ __forceinline__ const float* ks_sel(int s)
{
    if (s == 0) return g_f;
    return (s == 1) ? g_XA : g_XB;
}
__device__ __forceinline__ float* ks_sel_w(int s)
{
    return (s == 1) ? g_XA : g_XB;
}

__global__ __launch_bounds__(512) void ks_level_kernel(int d, int src_sel, int dst_sel)
{
    const float* __restrict__ src = ks_sel(src_sel);
    float* __restrict__ dst = ks_sel_w(dst_sel);
    const int c = blockIdx.x;
    const int shift = 1 << d;

    if (c < shift) {
        const int n = threadIdx.x;
        #pragma unroll
        for (int b = 0; b < B_SZ; b++)
            dst[((size_t)c * B_SZ + b) * N_DIM + n] = src[((size_t)c * B_SZ + b) * N_DIM + n];
        return;
    }

    __shared__ float xs[N_DIM * BPAD];
    const float* __restrict__ M = g_Mp + (size_t)d * N_DIM * N_DIM;
    const int bg = threadIdx.x & 3;
    const int rg = threadIdx.x >> 2;
    const int n0 = rg * 4;

    {
        const int k = threadIdx.x;
        const float* sp = src + (size_t)(c - shift) * B_SZ * N_DIM;
        #pragma unroll
        for (int b = 0; b < B_SZ; b++)
            xs[k * BPAD + b] = sp[(size_t)b * N_DIM + k];
    }
    __syncthreads();

    float acc0[4], acc1[4], acc2[4], acc3[4];
    #pragma unroll
    for (int bb = 0; bb < 4; bb++) {
        const float4 v = *reinterpret_cast<const float4*>(
            src + ((size_t)c * B_SZ + (bg*4 + bb)) * N_DIM + n0);
        acc0[bb] = v.x; acc1[bb] = v.y; acc2[bb] = v.z; acc3[bb] = v.w;
    }

    const float4* m0 = reinterpret_cast<const float4*>(M + (size_t)(n0 + 0) * N_DIM);
    const float4* m1 = reinterpret_cast<const float4*>(M + (size_t)(n0 + 1) * N_DIM);
    const float4* m2 = reinterpret_cast<const float4*>(M + (size_t)(n0 + 2) * N_DIM);
    const float4* m3 = reinterpret_cast<const float4*>(M + (size_t)(n0 + 3) * N_DIM);
    const float* xp = xs + bg * 4;

    #pragma unroll 2
    for (int k4 = 0; k4 < N_DIM / 4; k4++) {
        const float4 Av0 = m0[k4], Av1 = m1[k4], Av2 = m2[k4], Av3 = m3[k4];
        const int k = 4 * k4;
        #pragma unroll
        for (int kk = 0; kk < 4; kk++) {
            const float a0v = (&Av0.x)[kk], a1v = (&Av1.x)[kk],
                        a2v = (&Av2.x)[kk], a3v = (&Av3.x)[kk];
            const float4 hv = *reinterpret_cast<const float4*>(xp + (k + kk) * BPAD);
            acc0[0] += a0v*hv.x; acc0[1] += a0v*hv.y; acc0[2] += a0v*hv.z; acc0[3] += a0v*hv.w;
            acc1[0] += a1v*hv.x; acc1[1] += a1v*hv.y; acc1[2] += a1v*hv.z; acc1[3] += a1v*hv.w;
            acc2[0] += a2v*hv.x; acc2[1] += a2v*hv.y; acc2[2] += a2v*hv.z; acc2[3] += a2v*hv.w;
            acc3[0] += a3v*hv.x; acc3[1] += a3v*hv.y; acc3[2] += a3v*hv.z; acc3[3] += a3v*hv.w;
        }
    }

    #pragma unroll
    for (int bb = 0; bb < 4; bb++) {
        float4 v; v.x = acc0[bb]; v.y = acc1[bb]; v.z = acc2[bb]; v.w = acc3[bb];
        *reinterpret_cast<float4*>(
            dst + ((size_t)c * B_SZ + (bg*4 + bb)) * N_DIM + n0) = v;
    }
}

// ---------------- tf32 chunk scan: 2 chunks per CTA, A direct from L2 -------
// h in smem [col][k] (KSTR=516, conflict-free), tf32 split.
// No smem A: fragments loaded straight from blocked global (L2-resident, 2MB).
// Zero barriers in the k-loop; 2 barriers per step.
template <bool FIRST_PASS>
__global__ __launch_bounds__(512) void scan_tf32_kernel(float* __restrict__ out,
                                                        int out_size)
{
    extern __shared__ float smf[];
    float* h1s = smf;
    float* h2s = smf + H2_OFF;

    const int c0   = blockIdx.x * CPC;
    const int tid  = threadIdx.x;
    const int warp = tid >> 5;
    const int lane = tid & 31;
    const int g    = lane >> 2;          // groupID 0..7
    const int t    = lane & 3;           // threadID in group 0..3
    const int row0 = warp * 32;          // warp owns rows [row0, row0+32)

    // ---- init h split ----
    if (FIRST_PASS) {
        #pragma unroll
        for (int col = 0; col < NCOL; col++) {
            h1s[col * KSTR + tid] = 0.0f;
            h2s[col * KSTR + tid] = 0.0f;
        }
    } else {
        #pragma unroll
        for (int col = 0; col < NCOL; col++) {
            const int chunk = c0 + (col >> 4);
            const int b = col & 15;
            float v = 0.0f;
            if (chunk > 0)
                v = g_XA[(((size_t)(chunk - 1)) * B_SZ + b) * N_DIM + tid];
            const float v1 = tf32r(v);
            h1s[col * KSTR + tid] = v1;
            h2s[col * KSTR + tid] = tf32r(v - v1);
        }
    }
    __syncthreads();

    for (int j = 0; j < T_CH; j++) {
        const int tt0 = (c0 + 0) * T_CH + j;
        const int tt1 = (c0 + 1) * T_CH + j;

        // ---- acc init from bx[t][n][b] ----
        float acc[2][4][4];
        #pragma unroll
        for (int mt = 0; mt < 2; mt++) {
            const int n = row0 + mt * 16 + g;
            #pragma unroll
            for (int nt = 0; nt < 4; nt++) {
                const int ttx = (nt >= 2) ? tt1 : tt0;
                const int b = (nt & 1) * 8 + t * 2;
                const float2 vlo = *reinterpret_cast<const float2*>(
                    g_bx + ((size_t)ttx * N_DIM + n) * B_SZ + b);
                const float2 vhi = *reinterpret_cast<const float2*>(
                    g_bx + ((size_t)ttx * N_DIM + n + 8) * B_SZ + b);
                acc[mt][nt][0] = vlo.x; acc[mt][nt][1] = vlo.y;
                acc[mt][nt][2] = vhi.x; acc[mt][nt][3] = vhi.y;
            }
        }

        // ---- k loop: no barriers; A frags direct from global ----
        #pragma unroll 2
        for (int kc = 0; kc < 64; kc++) {
            const float* A1 = g_A1t + (size_t)kc * (N_DIM * 8);
            const float* A2 = g_A2t + (size_t)kc * (N_DIM * 8);
            const int kr = kc * 8;

            unsigned a1f[2][4], a2f[2][4];
            #pragma unroll
            for (int mt = 0; mt < 2; mt++) {
                const int rb = row0 + mt * 16;
                a1f[mt][0] = __float_as_uint(A1[(rb + g    ) * 8 + t    ]);
                a1f[mt][1] = __float_as_uint(A1[(rb + g + 8) * 8 + t    ]);
                a1f[mt][2] = __float_as_uint(A1[(rb + g    ) * 8 + t + 4]);
                a1f[mt][3] = __float_as_uint(A1[(rb + g + 8) * 8 + t + 4]);
                a2f[mt][0] = __float_as_uint(A2[(rb + g    ) * 8 + t    ]);
                a2f[mt][1] = __float_as_uint(A2[(rb + g + 8) * 8 + t    ]);
                a2f[mt][2] = __float_as_uint(A2[(rb + g    ) * 8 + t + 4]);
                a2f[mt][3] = __float_as_uint(A2[(rb + g + 8) * 8 + t + 4]);
            }

            unsigned b1f[4][2], b2f[4][2];
            #pragma unroll
            for (int nt = 0; nt < 4; nt++) {
                const int col = nt * 8 + g;
                b1f[nt][0] = __float_as_uint(h1s[col * KSTR + kr + t    ]);
                b1f[nt][1] = __float_as_uint(h1s[col * KSTR + kr + t + 4]);
                b2f[nt][0] = __float_as_uint(h2s[col * KSTR + kr + t    ]);
                b2f[nt][1] = __float_as_uint(h2s[col * KSTR + kr + t + 4]);
            }

            #pragma unroll
            for (int mt = 0; mt < 2; mt++) {
                #pragma unroll
                for (int nt = 0; nt < 4; nt++) {
                    MMATF32(acc[mt][nt], a1f[mt], b1f[nt]);
                    MMATF32(acc[mt][nt], a1f[mt], b2f[nt]);
                    MMATF32(acc[mt][nt], a2f[mt], b1f[nt]);
                }
            }
        }

        __syncthreads();   // all reads of h for this step complete

        // ---- write-back: h split, outputs, finals ----
        #pragma unroll
        for (int mt = 0; mt < 2; mt++) {
            #pragma unroll
            for (int nt = 0; nt < 4; nt++) {
                const int col = nt * 8 + t * 2;
                const int chunk = c0 + (nt >> 1);
                const int b = col & 15;
                const int ttx = chunk * T_CH + j;
                #pragma unroll
                for (int hh = 0; hh < 2; hh++) {
                    const int n = row0 + mt * 16 + g + hh * 8;
                    const float v0 = acc[mt][nt][hh * 2 + 0];
                    const float v1 = acc[mt][nt][hh * 2 + 1];
                    const float p0 = tf32r(v0), p1v = tf32r(v1);
                    h1s[(col    ) * KSTR + n] = p0;
                    h1s[(col + 1) * KSTR + n] = p1v;
                    h2s[(col    ) * KSTR + n] = tf32r(v0 - p0);
                    h2s[(col + 1) * KSTR + n] = tf32r(v1 - p1v);

                    if (!FIRST_PASS) {
                        out[((size_t)(b)     * L_LEN + ttx) * N_DIM + n] = v0;
                        out[((size_t)(b + 1) * L_LEN + ttx) * N_DIM + n] = v1;
                    }
                    if (FIRST_PASS && j == T_CH - 1) {
                        g_f[((size_t)chunk * B_SZ + b)     * N_DIM + n] = v0;
                        g_f[((size_t)chunk * B_SZ + b + 1) * N_DIM + n] = v1;
                    }
                    if (!FIRST_PASS && chunk == C_CH - 1 && j == T_CH - 1 &&
                        out_size >= OUT_MAIN + N_DIM * B_SZ) {
                        out[OUT_MAIN + (size_t)n * B_SZ + b]     = v0;
                        out[OUT_MAIN + (size_t)n * B_SZ + b + 1] = v1;
                    }
                }
            }
        }
        __syncthreads();   // h writes visible before next step's frag reads
    }
}

// ---------------- launch ----------------------------------------------------
extern "C" void kernel_launch(void* const* d_in, const int* in_sizes, int n_in,
                              void* d_out, int out_size)
{
    const float* x  = (const float*)d_in[0];   // (B, L, H)
    const float* A  = (const float*)d_in[1];   // (N, N)
    const float* Bm = (const float*)d_in[2];   // (N, H)
    float* out = (float*)d_out;

    cudaFuncSetAttribute(scan_tf32_kernel<true>,
                         cudaFuncAttributeMaxDynamicSharedMemorySize, SCAN_SMEM_BYTES);
    cudaFuncSetAttribute(scan_tf32_kernel<false>,
                         cudaFuncAttributeMaxDynamicSharedMemorySize, SCAN_SMEM_BYTES);

    dim3 sgrid(N_DIM / 32, N_DIM / 32);
    const int SCAN_GRID = C_CH / CPC;          // 128 CTAs

    prep_kernel<<<N_DIM * N_DIM / 256, 256>>>(A);
    proj_kernel<<<L_LEN, 512>>>(x, Bm);
    matsq_kernel<<<sgrid, 128>>>(A, 0, 1);                     // P1 = A^2
    matsq_kernel<<<sgrid, 128>>>(A, 1, 2);                     // P2 = A^4
    scan_tf32_kernel<true><<<SCAN_GRID, 512, SCAN_SMEM_BYTES>>>(nullptr, 0);

    matsq_kernel<<<sgrid, 128>>>(A, 2, 10);                    // Mp[0] = A^8
    matsq_kernel<<<sgrid, 128>>>(A, 10, 11);                   // A^16
    matsq_kernel<<<sgrid, 128>>>(A, 11, 12);                   // A^32
    matsq_kernel<<<sgrid, 128>>>(A, 12, 13);                   // A^64
    matsq_kernel<<<sgrid, 128>>>(A, 13, 14);                   // A^128
    matsq_kernel<<<sgrid, 128>>>(A, 14, 15);                   // A^256
    matsq_kernel<<<sgrid, 128>>>(A, 15, 16);                   // A^512
    matsq_kernel<<<sgrid, 128>>>(A, 16, 17);                   // A^1024

    // Kogge-Stone over 256 chunk finals: 8 levels, ends in XA
    ks_level_kernel<<<C_CH, 512>>>(0, 0, 2);   // f  -> XB
    ks_level_kernel<<<C_CH, 512>>>(1, 2, 1);   // XB -> XA
    ks_level_kernel<<<C_CH, 512>>>(2, 1, 2);
    ks_level_kernel<<<C_CH, 512>>>(3, 2, 1);
    ks_level_kernel<<<C_CH, 512>>>(4, 1, 2);
    ks_level_kernel<<<C_CH, 512>>>(5, 2, 1);
    ks_level_kernel<<<C_CH, 512>>>(6, 1, 2);
    ks_level_kernel<<<C_CH, 512>>>(7, 2, 1);   // final in XA

    scan_tf32_kernel<false><<<SCAN_GRID, 512, SCAN_SMEM_BYTES>>>(out, out_size);
}

// round 11
// speedup vs baseline: 1.7406x; 1.0775x over previous
#include <cuda_runtime.h>

// Problem constants
#define B_SZ    16
#define L_LEN   2048
#define H_DIM   512
#define N_DIM   512
#define T_CH    8                  // chunk length
#define C_CH    (L_LEN / T_CH)     // 256 chunks
#define CPC     2                  // chunks per CTA
#define OUT_MAIN (B_SZ * L_LEN * N_DIM)
#define BPAD    20                 // proj/ks smem pad (floats)

// scan smem: h only, [col][k] layout, KSTR conflict-free (516 ≡ 4 mod 32)
#define NCOL    (CPC * B_SZ)       // 32 columns per CTA
#define KSTR    516
#define H2_OFF  (NCOL * KSTR)      // 16512
#define SCAN_SMEM_BYTES (2 * NCOL * KSTR * 4)   // 132096

// ---------------- scratch (device globals; no allocations allowed) ----------
__device__ float g_bx[L_LEN * N_DIM * B_SZ];   // Bx projections  [t][n][b]
__device__ float g_f [C_CH * B_SZ * N_DIM];    // chunk local finals [c][b][n]
__device__ float g_XA[C_CH * B_SZ * N_DIM];    // Kogge-Stone ping
__device__ float g_XB[C_CH * B_SZ * N_DIM];    // Kogge-Stone pong
__device__ float g_P1[N_DIM * N_DIM];
__device__ float g_P2[N_DIM * N_DIM];
__device__ float g_Mp[8 * N_DIM * N_DIM];      // M^(2^d), M = A^8, d=0..7
// A splits packed in mma-fragment order: [kc(64)][tile16(32)][lane(32)][4]
__device__ float g_A1p[N_DIM * N_DIM];
__device__ float g_A2p[N_DIM * N_DIM];

// ---------------- tf32 helpers ----------------------------------------------
__device__ __forceinline__ float tf32r(float x)
{
    unsigned y;
    asm("cvt.rna.tf32.f32 %0, %1;" : "=r"(y) : "f"(x));
    return __uint_as_float(y);
}

#define MMATF32(d, a, b) \
    asm volatile("mma.sync.aligned.m16n8k8.row.col.f32.tf32.tf32.f32 " \
        "{%0,%1,%2,%3}, {%4,%5,%6,%7}, {%8,%9}, {%0,%1,%2,%3};" \
        : "+f"((d)[0]), "+f"((d)[1]), "+f"((d)[2]), "+f"((d)[3]) \
        : "r"((a)[0]), "r"((a)[1]), "r"((a)[2]), "r"((a)[3]), \
          "r"((b)[0]), "r"((b)[1]))

// ---------------- packed fp32x2 ----------------------------------------------
typedef unsigned long long u64;
#define FFMA2(acc, apk, hpk) \
    asm("fma.rn.f32x2 %0, %1, %2, %0;" : "+l"(acc) : "l"(apk), "l"(hpk))
#define PACK2(dst, f) \
    asm("mov.b64 %0, {%1, %1};" : "=l"(dst) : "f"(f))
#define PACKLOHI(dst, lo, hi) \
    asm("mov.b64 %0, {%1, %2};" : "=l"(dst) : "f"(lo), "f"(hi))
#define UNPK(lo, hi, src) \
    asm("mov.b64 {%0, %1}, %2;" : "=f"(lo), "=f"(hi) : "l"(src))

#define ONEK(base, off, c0v, c1v, c2v, c3v) do {                               \
    const ulonglong2 hvp = *reinterpret_cast<const ulonglong2*>((base) + (off) * BPAD); \
    u64 ap;                                                                    \
    PACK2(ap, c0v); FFMA2(acc0p[0], ap, hvp.x); FFMA2(acc0p[1], ap, hvp.y);    \
    PACK2(ap, c1v); FFMA2(acc1p[0], ap, hvp.x); FFMA2(acc1p[1], ap, hvp.y);    \
    PACK2(ap, c2v); FFMA2(acc2p[0], ap, hvp.x); FFMA2(acc2p[1], ap, hvp.y);    \
    PACK2(ap, c3v); FFMA2(acc3p[0], ap, hvp.x); FFMA2(acc3p[1], ap, hvp.y);    \
} while (0)

#define QUAD_FMA(base, k4) do {                                                \
    ONEK(base, 4*(k4) + 0, Av0.x, Av1.x, Av2.x, Av3.x);                        \
    ONEK(base, 4*(k4) + 1, Av0.y, Av1.y, Av2.y, Av3.y);                        \
    ONEK(base, 4*(k4) + 2, Av0.z, Av1.z, Av2.z, Av3.z);                        \
    ONEK(base, 4*(k4) + 3, Av0.w, Av1.w, Av2.w, Av3.w);                        \
} while (0)

// ---------------- prep: A (fp32) -> tf32 split, mma-fragment packed ----------
// dst index: ((kc*32 + m)*32 + lane)*4 + i
//   m = row>>4; r16 = row&15: g = r16&7, hi = r16>>3
//   t = kk&3, thi = kk>>2; lane = g*4 + t; i = hi + 2*thi
__global__ __launch_bounds__(256) void prep_kernel(const float* __restrict__ A)
{
    const int idx = blockIdx.x * 256 + threadIdx.x;
    const int row = idx >> 9;
    const int k   = idx & 511;
    const int kc  = k >> 3, kk = k & 7;
    const float a = A[idx];
    const float a1 = tf32r(a);
    const float a2 = tf32r(a - a1);

    const int m    = row >> 4;
    const int r16  = row & 15;
    const int g    = r16 & 7;
    const int hi   = r16 >> 3;
    const int t    = kk & 3;
    const int thi  = kk >> 2;
    const int lane = g * 4 + t;
    const int i    = hi + 2 * thi;
    const int dst  = ((kc * 32 + m) * 32 + lane) * 4 + i;
    g_A1p[dst] = a1;
    g_A2p[dst] = a2;
}

// ---------------- Phase 1: bx[t][n][b] = sum_h Bm[n][h] * x[b][t][h] -------
__global__ __launch_bounds__(512) void proj_kernel(const float* __restrict__ x,
                                                   const float* __restrict__ Bm)
{
    __shared__ float xs[H_DIM * BPAD];
    const int t  = blockIdx.x;
    const int bg = threadIdx.x & 3;
    const int rg = threadIdx.x >> 2;

    {
        const int k = threadIdx.x;
        #pragma unroll
        for (int b = 0; b < B_SZ; b++)
            xs[k * BPAD + b] = x[((size_t)b * L_LEN + t) * H_DIM + k];
    }
    __syncthreads();

    u64 acc0p[2] = {0,0}, acc1p[2] = {0,0}, acc2p[2] = {0,0}, acc3p[2] = {0,0};

    const int n0 = rg * 4;
    const float4* w0 = reinterpret_cast<const float4*>(Bm + (size_t)(n0 + 0) * H_DIM);
    const float4* w1 = reinterpret_cast<const float4*>(Bm + (size_t)(n0 + 1) * H_DIM);
    const float4* w2 = reinterpret_cast<const float4*>(Bm + (size_t)(n0 + 2) * H_DIM);
    const float4* w3 = reinterpret_cast<const float4*>(Bm + (size_t)(n0 + 3) * H_DIM);
    const float* xp = xs + bg * 4;

    #pragma unroll 2
    for (int k4 = 0; k4 < H_DIM / 4; k4++) {
        const float4 Av0 = w0[k4], Av1 = w1[k4], Av2 = w2[k4], Av3 = w3[k4];
        QUAD_FMA(xp, k4);
    }

    {
        float l0,h0,l1,h1;
        float4 v;
        UNPK(l0,h0, acc0p[0]); UNPK(l1,h1, acc0p[1]);
        v.x=l0; v.y=h0; v.z=l1; v.w=h1;
        *reinterpret_cast<float4*>(g_bx + ((size_t)t * N_DIM + n0 + 0) * B_SZ + bg*4) = v;
        UNPK(l0,h0, acc1p[0]); UNPK(l1,h1, acc1p[1]);
        v.x=l0; v.y=h0; v.z=l1; v.w=h1;
        *reinterpret_cast<float4*>(g_bx + ((size_t)t * N_DIM + n0 + 1) * B_SZ + bg*4) = v;
        UNPK(l0,h0, acc2p[0]); UNPK(l1,h1, acc2p[1]);
        v.x=l0; v.y=h0; v.z=l1; v.w=h1;
        *reinterpret_cast<float4*>(g_bx + ((size_t)t * N_DIM + n0 + 2) * B_SZ + bg*4) = v;
        UNPK(l0,h0, acc3p[0]); UNPK(l1,h1, acc3p[1]);
        v.x=l0; v.y=h0; v.z=l1; v.w=h1;
        *reinterpret_cast<float4*>(g_bx + ((size_t)t * N_DIM + n0 + 3) * B_SZ + bg*4) = v;
    }
}

// ---------------- SGEMM: Y = X @ X (512x512), 32x32 tiles -------------------
__device__ __forceinline__ const float* mat_sel(const float* Aext, int s)
{
    if (s == 0) return Aext;
    if (s == 1) return g_P1;
    if (s == 2) return g_P2;
    return g_Mp + (size_t)(s - 10) * N_DIM * N_DIM;
}
__device__ __forceinline__ float* mat_sel_w(int s)
{
    if (s == 1) return g_P1;
    if (s == 2) return g_P2;
    return g_Mp + (size_t)(s - 10) * N_DIM * N_DIM;
}

__global__ __launch_bounds__(128) void matsq_kernel(const float* __restrict__ Aext,
                                                    int src_sel, int dst_sel)
{
    const float* __restrict__ X = mat_sel(Aext, src_sel);
    float* __restrict__ Y = mat_sel_w(dst_sel);

    __shared__ float As[32][34];
    __shared__ float Bs[32][36];
    const int tid = threadIdx.x;
    const int tx = tid & 7;
    const int ty = tid >> 3;
    const int i0 = blockIdx.y * 32, j0 = blockIdx.x * 32;

    u64 acc0[2] = {0,0}, acc1[2] = {0,0};

    const int lrow = tid >> 2;
    const int lq   = tid & 3;

    for (int kt = 0; kt < N_DIM; kt += 32) {
        {
            const float4 v1 = *reinterpret_cast<const float4*>(X + (size_t)(i0 + lrow) * N_DIM + kt + lq * 8);
            const float4 v2 = *reinterpret_cast<const float4*>(X + (size_t)(i0 + lrow) * N_DIM + kt + lq * 8 + 4);
            As[lq*8 + 0][lrow] = v1.x; As[lq*8 + 1][lrow] = v1.y;
            As[lq*8 + 2][lrow] = v1.z; As[lq*8 + 3][lrow] = v1.w;
            As[lq*8 + 4][lrow] = v2.x; As[lq*8 + 5][lrow] = v2.y;
            As[lq*8 + 6][lrow] = v2.z; As[lq*8 + 7][lrow] = v2.w;
        }
        {
            const float4 v1 = *reinterpret_cast<const float4*>(X + (size_t)(kt + lrow) * N_DIM + j0 + lq * 8);
            const float4 v2 = *reinterpret_cast<const float4*>(X + (size_t)(kt + lrow) * N_DIM + j0 + lq * 8 + 4);
            *reinterpret_cast<float4*>(&Bs[lrow][lq*8])     = v1;
            *reinterpret_cast<float4*>(&Bs[lrow][lq*8 + 4]) = v2;
        }
        __syncthreads();

        #pragma unroll
        for (int kk = 0; kk < 32; kk++) {
            const float2 a = *reinterpret_cast<const float2*>(&As[kk][ty * 2]);
            const ulonglong2 bv = *reinterpret_cast<const ulonglong2*>(&Bs[kk][tx * 4]);
            u64 ap;
            PACK2(ap, a.x); FFMA2(acc0[0], ap, bv.x); FFMA2(acc0[1], ap, bv.y);
            PACK2(ap, a.y); FFMA2(acc1[0], ap, bv.x); FFMA2(acc1[1], ap, bv.y);
        }
        __syncthreads();
    }

    {
        float l0,h0,l1,h1;
        UNPK(l0,h0, acc0[0]); UNPK(l1,h1, acc0[1]);
        float4 v; v.x=l0; v.y=h0; v.z=l1; v.w=h1;
        *reinterpret_cast<float4*>(Y + (size_t)(i0 + ty*2 + 0) * N_DIM + j0 + tx*4) = v;
        UNPK(l0,h0, acc1[0]); UNPK(l1,h1, acc1[1]);
        v.x=l0; v.y=h0; v.z=l1; v.w=h1;
        *reinterpret_cast<float4*>(Y + (size_t)(i0 + ty*2 + 1) * N_DIM + j0 + tx*4) = v;
    }
}

// ---------------- Kogge-Stone level (f32x2): x'_c = M x_{c-2^d} + x_c ------
__device__ __forceinline__ const float* ks_sel(int s)
{
    if (s == 0) return g_f;
    return (s == 1) ? g_XA : g_XB;
}
__device__ __forceinline__ float* ks_sel_w(int s)
{
    return (s == 1) ? g_XA : g_XB;
}

__global__ __launch_bounds__(512) void ks_level_kernel(int d, int src_sel, int dst_sel)
{
    const float* __restrict__ src = ks_sel(src_sel);
    float* __restrict__ dst = ks_sel_w(dst_sel);
    const int c = blockIdx.x;
    const int shift = 1 << d;

    if (c < shift) {
        const int n = threadIdx.x;
        #pragma unroll
        for (int b = 0; b < B_SZ; b++)
            dst[((size_t)c * B_SZ + b) * N_DIM + n] = src[((size_t)c * B_SZ + b) * N_DIM + n];
        return;
    }

    __shared__ float xs[N_DIM * BPAD];         // x_{c-shift} as [k][b]
    const float* __restrict__ M = g_Mp + (size_t)d * N_DIM * N_DIM;
    const int bg = threadIdx.x & 3;
    const int rg = threadIdx.x >> 2;
    const int n0 = rg * 4;

    {
        const int k = threadIdx.x;
        const float* sp = src + (size_t)(c - shift) * B_SZ * N_DIM;
        #pragma unroll
        for (int b = 0; b < B_SZ; b++)
            xs[k * BPAD + b] = sp[(size_t)b * N_DIM + k];
    }
    __syncthreads();

    u64 acc0p[2], acc1p[2], acc2p[2], acc3p[2];
    #pragma unroll
    for (int bp = 0; bp < 2; bp++) {
        const float4 vL = *reinterpret_cast<const float4*>(
            src + ((size_t)c * B_SZ + (bg*4 + 2*bp))     * N_DIM + n0);
        const float4 vH = *reinterpret_cast<const float4*>(
            src + ((size_t)c * B_SZ + (bg*4 + 2*bp + 1)) * N_DIM + n0);
        PACKLOHI(acc0p[bp], vL.x, vH.x);
        PACKLOHI(acc1p[bp], vL.y, vH.y);
        PACKLOHI(acc2p[bp], vL.z, vH.z);
        PACKLOHI(acc3p[bp], vL.w, vH.w);
    }

    const float4* m0 = reinterpret_cast<const float4*>(M + (size_t)(n0 + 0) * N_DIM);
    const float4* m1 = reinterpret_cast<const float4*>(M + (size_t)(n0 + 1) * N_DIM);
    const float4* m2 = reinterpret_cast<const float4*>(M + (size_t)(n0 + 2) * N_DIM);
    const float4* m3 = reinterpret_cast<const float4*>(M + (size_t)(n0 + 3) * N_DIM);
    const float* xp = xs + bg * 4;

    #pragma unroll 2
    for (int k4 = 0; k4 < N_DIM / 4; k4++) {
        const float4 Av0 = m0[k4], Av1 = m1[k4], Av2 = m2[k4], Av3 = m3[k4];
        QUAD_FMA(xp, k4);
    }

    #pragma unroll
    for (int bp = 0; bp < 2; bp++) {
        float l0,h0,l1,h1,l2,h2,l3,h3;
        UNPK(l0,h0, acc0p[bp]); UNPK(l1,h1, acc1p[bp]);
        UNPK(l2,h2, acc2p[bp]); UNPK(l3,h3, acc3p[bp]);
        float4 vL; vL.x=l0; vL.y=l1; vL.z=l2; vL.w=l3;
        float4 vH; vH.x=h0; vH.y=h1; vH.z=h2; vH.w=h3;
        *reinterpret_cast<float4*>(dst + ((size_t)c * B_SZ + (bg*4 + 2*bp))     * N_DIM + n0) = vL;
        *reinterpret_cast<float4*>(dst + ((size_t)c * B_SZ + (bg*4 + 2*bp + 1)) * N_DIM + n0) = vH;
    }
}

// ---------------- tf32 chunk scan: 2 chunks/CTA, frag-packed A from L2 ------
template <bool FIRST_PASS>
__global__ __launch_bounds__(512) void scan_tf32_kernel(float* __restrict__ out,
                                                        int out_size)
{
    extern __shared__ float smf[];
    float* h1s = smf;
    float* h2s = smf + H2_OFF;

    const int c0   = blockIdx.x * CPC;
    const int tid  = threadIdx.x;
    const int warp = tid >> 5;
    const int lane = tid & 31;
    const int g    = lane >> 2;
    const int t    = lane & 3;
    const int row0 = warp * 32;

    // ---- init h split ----
    if (FIRST_PASS) {
        #pragma unroll
        for (int col = 0; col < NCOL; col++) {
            h1s[col * KSTR + tid] = 0.0f;
            h2s[col * KSTR + tid] = 0.0f;
        }
    } else {
        #pragma unroll
        for (int col = 0; col < NCOL; col++) {
            const int chunk = c0 + (col >> 4);
            const int b = col & 15;
            float v = 0.0f;
            if (chunk > 0)
                v = g_XA[(((size_t)(chunk - 1)) * B_SZ + b) * N_DIM + tid];
            const float v1 = tf32r(v);
            h1s[col * KSTR + tid] = v1;
            h2s[col * KSTR + tid] = tf32r(v - v1);
        }
    }
    __syncthreads();

    for (int j = 0; j < T_CH; j++) {
        const int tt0 = (c0 + 0) * T_CH + j;
        const int tt1 = (c0 + 1) * T_CH + j;

        // ---- acc init from bx[t][n][b] ----
        float acc[2][4][4];
        #pragma unroll
        for (int mt = 0; mt < 2; mt++) {
            const int n = row0 + mt * 16 + g;
            #pragma unroll
            for (int nt = 0; nt < 4; nt++) {
                const int ttx = (nt >= 2) ? tt1 : tt0;
                const int b = (nt & 1) * 8 + t * 2;
                const float2 vlo = *reinterpret_cast<const float2*>(
                    g_bx + ((size_t)ttx * N_DIM + n) * B_SZ + b);
                const float2 vhi = *reinterpret_cast<const float2*>(
                    g_bx + ((size_t)ttx * N_DIM + n + 8) * B_SZ + b);
                acc[mt][nt][0] = vlo.x; acc[mt][nt][1] = vlo.y;
                acc[mt][nt][2] = vhi.x; acc[mt][nt][3] = vhi.y;
            }
        }

        // ---- k loop: no barriers; frag-packed A, one LDG.128 per fragment ---
        #pragma unroll 2
        for (int kc = 0; kc < 64; kc++) {
            const int kr = kc * 8;

            uint4 a1f[2], a2f[2];
            #pragma unroll
            for (int mt = 0; mt < 2; mt++) {
                const int m = warp * 2 + mt;                 // 16-row tile index
                const size_t fo = (((size_t)kc * 32 + m) * 32 + lane) * 4;
                a1f[mt] = *reinterpret_cast<const uint4*>(g_A1p + fo);
                a2f[mt] = *reinterpret_cast<const uint4*>(g_A2p + fo);
            }

            unsigned b1f[4][2], b2f[4][2];
            #pragma unroll
            for (int nt = 0; nt < 4; nt++) {
                const int col = nt * 8 + g;
                b1f[nt][0] = __float_as_uint(h1s[col * KSTR + kr + t    ]);
                b1f[nt][1] = __float_as_uint(h1s[col * KSTR + kr + t + 4]);
                b2f[nt][0] = __float_as_uint(h2s[col * KSTR + kr + t    ]);
                b2f[nt][1] = __float_as_uint(h2s[col * KSTR + kr + t + 4]);
            }

            #pragma unroll
            for (int mt = 0; mt < 2; mt++) {
                const unsigned* a1 = reinterpret_cast<const unsigned*>(&a1f[mt]);
                const unsigned* a2 = reinterpret_cast<const unsigned*>(&a2f[mt]);
                #pragma unroll
                for (int nt = 0; nt < 4; nt++) {
                    MMATF32(acc[mt][nt], a1, b1f[nt]);
                    MMATF32(acc[mt][nt], a1, b2f[nt]);
                    MMATF32(acc[mt][nt], a2, b1f[nt]);
                }
            }
        }

        __syncthreads();   // all reads of h for this step complete

        // ---- write-back: h split, outputs, finals ----
        #pragma unroll
        for (int mt = 0; mt < 2; mt++) {
            #pragma unroll
            for (int nt = 0; nt < 4; nt++) {
                const int col = nt * 8 + t * 2;
                const int chunk = c0 + (nt >> 1);
                const int b = col & 15;
                const int ttx = chunk * T_CH + j;
                #pragma unroll
                for (int hh = 0; hh < 2; hh++) {
                    const int n = row0 + mt * 16 + g + hh * 8;
                    const float v0 = acc[mt][nt][hh * 2 + 0];
                    const float v1 = acc[mt][nt][hh * 2 + 1];
                    const float p0 = tf32r(v0), p1v = tf32r(v1);
                    h1s[(col    ) * KSTR + n] = p0;
                    h1s[(col + 1) * KSTR + n] = p1v;
                    h2s[(col    ) * KSTR + n] = tf32r(v0 - p0);
                    h2s[(col + 1) * KSTR + n] = tf32r(v1 - p1v);

                    if (!FIRST_PASS) {
                        out[((size_t)(b)     * L_LEN + ttx) * N_DIM + n] = v0;
                        out[((size_t)(b + 1) * L_LEN + ttx) * N_DIM + n] = v1;
                    }
                    if (FIRST_PASS && j == T_CH - 1) {
                        g_f[((size_t)chunk * B_SZ + b)     * N_DIM + n] = v0;
                        g_f[((size_t)chunk * B_SZ + b + 1) * N_DIM + n] = v1;
                    }
                    if (!FIRST_PASS && chunk == C_CH - 1 && j == T_CH - 1 &&
                        out_size >= OUT_MAIN + N_DIM * B_SZ) {
                        out[OUT_MAIN + (size_t)n * B_SZ + b]     = v0;
                        out[OUT_MAIN + (size_t)n * B_SZ + b + 1] = v1;
                    }
                }
            }
        }
        __syncthreads();   // h writes visible before next step's frag reads
    }
}

// ---------------- launch ----------------------------------------------------
extern "C" void kernel_launch(void* const* d_in, const int* in_sizes, int n_in,
                              void* d_out, int out_size)
{
    const float* x  = (const float*)d_in[0];   // (B, L, H)
    const float* A  = (const float*)d_in[1];   // (N, N)
    const float* Bm = (const float*)d_in[2];   // (N, H)
    float* out = (float*)d_out;

    cudaFuncSetAttribute(scan_tf32_kernel<true>,
                         cudaFuncAttributeMaxDynamicSharedMemorySize, SCAN_SMEM_BYTES);
    cudaFuncSetAttribute(scan_tf32_kernel<false>,
                         cudaFuncAttributeMaxDynamicSharedMemorySize, SCAN_SMEM_BYTES);

    dim3 sgrid(N_DIM / 32, N_DIM / 32);
    const int SCAN_GRID = C_CH / CPC;          // 128 CTAs

    // launches #1..#5, then scan1 as launch #6 (ncu -s 5 -c 1 captures it)
    prep_kernel<<<N_DIM * N_DIM / 256, 256>>>(A);              // 1
    proj_kernel<<<L_LEN, 512>>>(x, Bm);                        // 2
    matsq_kernel<<<sgrid, 128>>>(A, 0, 1);                     // 3: P1 = A^2
    matsq_kernel<<<sgrid, 128>>>(A, 1, 2);                     // 4: P2 = A^4
    matsq_kernel<<<sgrid, 128>>>(A, 2, 10);                    // 5: Mp[0] = A^8
    scan_tf32_kernel<true><<<SCAN_GRID, 512, SCAN_SMEM_BYTES>>>(nullptr, 0);  // 6

    matsq_kernel<<<sgrid, 128>>>(A, 10, 11);                   // A^16
    matsq_kernel<<<sgrid, 128>>>(A, 11, 12);                   // A^32
    matsq_kernel<<<sgrid, 128>>>(A, 12, 13);                   // A^64
    matsq_kernel<<<sgrid, 128>>>(A, 13, 14);                   // A^128
    matsq_kernel<<<sgrid, 128>>>(A, 14, 15);                   // A^256
    matsq_kernel<<<sgrid, 128>>>(A, 15, 16);                   // A^512
    matsq_kernel<<<sgrid, 128>>>(A, 16, 17);                   // A^1024

    // Kogge-Stone over 256 chunk finals: 8 levels, ends in XA
    ks_level_kernel<<<C_CH, 512>>>(0, 0, 2);   // f  -> XB
    ks_level_kernel<<<C_CH, 512>>>(1, 2, 1);   // XB -> XA
    ks_level_kernel<<<C_CH, 512>>>(2, 1, 2);
    ks_level_kernel<<<C_CH, 512>>>(3, 2, 1);
    ks_level_kernel<<<C_CH, 512>>>(4, 1, 2);
    ks_level_kernel<<<C_CH, 512>>>(5, 2, 1);
    ks_level_kernel<<<C_CH, 512>>>(6, 1, 2);
    ks_level_kernel<<<C_CH, 512>>>(7, 2, 1);   // final in XA

    scan_tf32_kernel<false><<<SCAN_GRID, 512, SCAN_SMEM_BYTES>>>(out, out_size);
}